// round 11
// baseline (speedup 1.0000x reference)
#include <cuda_runtime.h>
#include <cstdint>

// Elementwise ReLU, HBM-bound streaming kernel. FINAL CONFIG (= R5 best).
// 2^27 fp32 = 1 GiB traffic (512 MiB R + 512 MiB W).
//
// Measured design-space (kernel us / DRAM%):
//   ldg/default  unroll4 occ8 : 165.3 / 78.4
//   ldcs/stcs    unroll8 occ5 : 166.7 / 77.6
//   ldg/stcs     unroll4 occ8 : 161.7 / 79.9   <- THIS KERNEL (best)
//   ldcs/stcs    unroll4 occ8 : 164.9 / 78.5
// Conclusion: evict-first on the WRITE stream only. ~6.3 TB/s = the mixed
// R/W HBM ceiling; occupancy, unroll depth, and L2 alloc policy are all
// non-factors at this point.

__global__ __launch_bounds__(256, 8) void relu_f4_kernel(
    const float4* __restrict__ in, float4* __restrict__ out, int n4)
{
    const int idx = blockIdx.x * blockDim.x + threadIdx.x;
    const int stride = gridDim.x * blockDim.x;
    const int stride4 = stride * 4;

    int i = idx;
    #pragma unroll 1
    for (; i + 3 * stride < n4; i += stride4) {
        float4 a = __ldg(&in[i]);
        float4 b = __ldg(&in[i + stride]);
        float4 c = __ldg(&in[i + 2 * stride]);
        float4 d = __ldg(&in[i + 3 * stride]);
        a.x = fmaxf(a.x, 0.f); a.y = fmaxf(a.y, 0.f); a.z = fmaxf(a.z, 0.f); a.w = fmaxf(a.w, 0.f);
        b.x = fmaxf(b.x, 0.f); b.y = fmaxf(b.y, 0.f); b.z = fmaxf(b.z, 0.f); b.w = fmaxf(b.w, 0.f);
        c.x = fmaxf(c.x, 0.f); c.y = fmaxf(c.y, 0.f); c.z = fmaxf(c.z, 0.f); c.w = fmaxf(c.w, 0.f);
        d.x = fmaxf(d.x, 0.f); d.y = fmaxf(d.y, 0.f); d.z = fmaxf(d.z, 0.f); d.w = fmaxf(d.w, 0.f);
        __stcs(&out[i],              a);
        __stcs(&out[i + stride],     b);
        __stcs(&out[i + 2 * stride], c);
        __stcs(&out[i + 3 * stride], d);
    }
    for (; i < n4; i += stride) {
        float4 a = __ldg(&in[i]);
        a.x = fmaxf(a.x, 0.f); a.y = fmaxf(a.y, 0.f);
        a.z = fmaxf(a.z, 0.f); a.w = fmaxf(a.w, 0.f);
        __stcs(&out[i], a);
    }
}

__global__ __launch_bounds__(256) void relu_scalar_kernel(
    const float* __restrict__ in, float* __restrict__ out, int n, int start)
{
    int i = start + blockIdx.x * blockDim.x + threadIdx.x;
    if (i < n) out[i] = fmaxf(__ldg(&in[i]), 0.f);
}

extern "C" void kernel_launch(void* const* d_in, const int* in_sizes, int n_in,
                              void* d_out, int out_size)
{
    const float* in = (const float*)d_in[0];
    float* out = (float*)d_out;
    int n = in_sizes[0];

    int n4 = n / 4;
    if (n4 > 0) {
        const int threads = 256;
        int blocks = 148 * 8;   // one full wave at occ 8
        int needed = (n4 + threads - 1) / threads;
        if (blocks > needed) blocks = needed;
        relu_f4_kernel<<<blocks, threads>>>(
            (const float4*)in, (float4*)out, n4);
    }
    int rem = n - n4 * 4;
    if (rem > 0) {
        relu_scalar_kernel<<<(rem + 255) / 256, 256>>>(in, out, n, n4 * 4);
    }
}

// round 12
// speedup vs baseline: 1.1333x; 1.1333x over previous
#include <cuda_runtime.h>
#include <cstdint>

// Elementwise ReLU, HBM-bound. 2^27 fp32 = 1 GiB traffic.
//
// Rounds 1-9 established: all cache-policy / unroll / occupancy variants sit
// at ~164 +/- 3 us kernel (~6.2 TB/s, the mixed R/W HBM ceiling). Run-to-run
// noise is +/-3us (identical binary: 161.7 vs 166.5).
//
// This round tests the last structural axis: FLAT kernel (1 float4/thread,
// 131072 CTAs) instead of 1-wave grid-stride (1184 long CTAs). Long-CTA
// designs pay the cross-CTA L1tex-queue spread (spr_max ~1.3 at oe=8,
// MLP_p1=4): the slowest CTA defines kernel time. Tiny CTAs let the
// work-stealing scheduler balance continuously -> no long tail.

__global__ __launch_bounds__(256, 8) void relu_flat_kernel(
    const float4* __restrict__ in, float4* __restrict__ out, int n4)
{
    int i = blockIdx.x * blockDim.x + threadIdx.x;
    if (i < n4) {
        float4 a = __ldg(&in[i]);
        a.x = fmaxf(a.x, 0.f);
        a.y = fmaxf(a.y, 0.f);
        a.z = fmaxf(a.z, 0.f);
        a.w = fmaxf(a.w, 0.f);
        __stcs(&out[i], a);
    }
}

__global__ __launch_bounds__(256) void relu_scalar_kernel(
    const float* __restrict__ in, float* __restrict__ out, int n, int start)
{
    int i = start + blockIdx.x * blockDim.x + threadIdx.x;
    if (i < n) out[i] = fmaxf(__ldg(&in[i]), 0.f);
}

extern "C" void kernel_launch(void* const* d_in, const int* in_sizes, int n_in,
                              void* d_out, int out_size)
{
    const float* in = (const float*)d_in[0];
    float* out = (float*)d_out;
    int n = in_sizes[0];

    int n4 = n / 4;          // 2^25 for this problem
    if (n4 > 0) {
        const int threads = 256;
        int blocks = (n4 + threads - 1) / threads;   // 131072
        relu_flat_kernel<<<blocks, threads>>>(
            (const float4*)in, (float4*)out, n4);
    }
    int rem = n - n4 * 4;
    if (rem > 0) {
        relu_scalar_kernel<<<(rem + 255) / 256, 256>>>(in, out, n, n4 * 4);
    }
}

// round 13
// speedup vs baseline: 1.1496x; 1.0144x over previous
#include <cuda_runtime.h>
#include <cstdint>

// Elementwise ReLU, HBM-bound. 2^27 fp32 = 1 GiB traffic.
//
// Evidence trail:
//   grid-stride (1184 long CTAs), any cache policy: ~164 +/- 3 us, DRAM ~78.5%
//   flat 1xf4/thread (131072 CTAs):                 156.8 us,     DRAM 82.0%  <- structural win
// Long CTAs pay cross-CTA L1tex-queue spread; tiny CTAs rebalance via
// work-stealing. This round: flat with 2 independent block-strided float4
// loads per thread (65536 CTAs) -> amortize per-CTA fixed cost over 8KB
// while keeping CTAs short. Load via __ldg, store evict-first (.cs).

__global__ __launch_bounds__(256, 8) void relu_flat2_kernel(
    const float4* __restrict__ in, float4* __restrict__ out, int n4)
{
    // Each CTA covers 2*256 consecutive float4s; thread t handles
    // base+t and base+t+256 (both warp-coalesced 128B segments).
    int base = blockIdx.x * (blockDim.x * 2) + threadIdx.x;
    int i0 = base;
    int i1 = base + blockDim.x;

    if (i1 < n4) {
        float4 a = __ldg(&in[i0]);
        float4 b = __ldg(&in[i1]);
        a.x = fmaxf(a.x, 0.f); a.y = fmaxf(a.y, 0.f);
        a.z = fmaxf(a.z, 0.f); a.w = fmaxf(a.w, 0.f);
        b.x = fmaxf(b.x, 0.f); b.y = fmaxf(b.y, 0.f);
        b.z = fmaxf(b.z, 0.f); b.w = fmaxf(b.w, 0.f);
        __stcs(&out[i0], a);
        __stcs(&out[i1], b);
    } else if (i0 < n4) {
        float4 a = __ldg(&in[i0]);
        a.x = fmaxf(a.x, 0.f); a.y = fmaxf(a.y, 0.f);
        a.z = fmaxf(a.z, 0.f); a.w = fmaxf(a.w, 0.f);
        __stcs(&out[i0], a);
    }
}

__global__ __launch_bounds__(256) void relu_scalar_kernel(
    const float* __restrict__ in, float* __restrict__ out, int n, int start)
{
    int i = start + blockIdx.x * blockDim.x + threadIdx.x;
    if (i < n) out[i] = fmaxf(__ldg(&in[i]), 0.f);
}

extern "C" void kernel_launch(void* const* d_in, const int* in_sizes, int n_in,
                              void* d_out, int out_size)
{
    const float* in = (const float*)d_in[0];
    float* out = (float*)d_out;
    int n = in_sizes[0];

    int n4 = n / 4;          // 2^25 here
    if (n4 > 0) {
        const int threads = 256;
        const int per_cta = threads * 2;
        int blocks = (n4 + per_cta - 1) / per_cta;   // 65536
        relu_flat2_kernel<<<blocks, threads>>>(
            (const float4*)in, (float4*)out, n4);
    }
    int rem = n - n4 * 4;
    if (rem > 0) {
        relu_scalar_kernel<<<(rem + 255) / 256, 256>>>(in, out, n, n4 * 4);
    }
}